// round 5
// baseline (speedup 1.0000x reference)
#include <cuda_runtime.h>

// TokenMixer: out = x_pos * (1 - sigmoid( <x_pre,x_pos> / (||x_pre||*||x_pos||) ))
// Shapes: [N=4096, B=16, C=512] f32. One warp per row, persistent grid-stride.
// R5: cross-row software pipelining. Each warp's reduce tail (~150 cyc of
// shfl/sqrt/exp with zero outstanding loads) is covered by issuing the NEXT
// row's 8 loads before the reduce. b-registers die after the partials; the
// store path re-loads x_pos (L1/L2 hit from ~100 cycles earlier) to keep
// register pressure inside __launch_bounds__(256,5) (<=51 regs, 40 warps/SM).

#define ROWS_TOTAL (4096 * 16)
#define F4_PER_ROW 128   // 512 floats / 4
#define WARPS_PER_BLOCK 8
#define GRID_BLOCKS (152 * 8)   // GB300: 152 SMs

__global__ __launch_bounds__(WARPS_PER_BLOCK * 32, 5)
void token_mixer_kernel(const float4* __restrict__ pre,
                        const float4* __restrict__ pos,
                        float4* __restrict__ out) {
    const int lane = threadIdx.x & 31;
    const int gw   = blockIdx.x * WARPS_PER_BLOCK + (threadIdx.x >> 5);
    const int W    = GRID_BLOCKS * WARPS_PER_BLOCK;   // total warps = 9728

    int row = gw;
    if (row >= ROWS_TOTAL) return;

    size_t base = (size_t)row * F4_PER_ROW + lane;

    // Prologue: load current row.
    float4 a0 = pre[base      ], b0 = pos[base      ];
    float4 a1 = pre[base +  32], b1 = pos[base +  32];
    float4 a2 = pre[base +  64], b2 = pos[base +  64];
    float4 a3 = pre[base +  96], b3 = pos[base +  96];

    for (;;) {
        // Partials — a* and b* die here.
        float dot, sa, sb;
        dot  = a0.x*b0.x + a0.y*b0.y + a0.z*b0.z + a0.w*b0.w;
        sa   = a0.x*a0.x + a0.y*a0.y + a0.z*a0.z + a0.w*a0.w;
        sb   = b0.x*b0.x + b0.y*b0.y + b0.z*b0.z + b0.w*b0.w;
        dot += a1.x*b1.x + a1.y*b1.y + a1.z*b1.z + a1.w*b1.w;
        sa  += a1.x*a1.x + a1.y*a1.y + a1.z*a1.z + a1.w*a1.w;
        sb  += b1.x*b1.x + b1.y*b1.y + b1.z*b1.z + b1.w*b1.w;
        dot += a2.x*b2.x + a2.y*b2.y + a2.z*b2.z + a2.w*b2.w;
        sa  += a2.x*a2.x + a2.y*a2.y + a2.z*a2.z + a2.w*a2.w;
        sb  += b2.x*b2.x + b2.y*b2.y + b2.z*b2.z + b2.w*b2.w;
        dot += a3.x*b3.x + a3.y*b3.y + a3.z*b3.z + a3.w*b3.w;
        sa  += a3.x*a3.x + a3.y*a3.y + a3.z*a3.z + a3.w*a3.w;
        sb  += b3.x*b3.x + b3.y*b3.y + b3.z*b3.z + b3.w*b3.w;

        // Issue NEXT row's loads now — they fly during the reduce tail below.
        const int next = row + W;
        const bool more = next < ROWS_TOTAL;
        const size_t nbase = (size_t)next * F4_PER_ROW + lane;
        if (more) {
            a0 = pre[nbase      ]; b0 = pos[nbase      ];
            a1 = pre[nbase +  32]; b1 = pos[nbase +  32];
            a2 = pre[nbase +  64]; b2 = pos[nbase +  64];
            a3 = pre[nbase +  96]; b3 = pos[nbase +  96];
        }

        // Warp tree-reduce the three scalars (serial tail, loads in flight).
        #pragma unroll
        for (int off = 16; off > 0; off >>= 1) {
            dot += __shfl_xor_sync(0xffffffffu, dot, off);
            sa  += __shfl_xor_sync(0xffffffffu, sa,  off);
            sb  += __shfl_xor_sync(0xffffffffu, sb,  off);
        }

        const float na = fmaxf(sqrtf(sa), 1e-12f);
        const float nb = fmaxf(sqrtf(sb), 1e-12f);
        const float d  = dot / (na * nb);
        // 1 - sigmoid(d) = 1 / (1 + exp(d))
        const float w  = 1.0f / (1.0f + __expf(d));

        // Store: re-load x_pos for the CURRENT row (L1/L2 hit), scale, write.
        {
            float4 c;
            c = pos[base      ]; c.x *= w; c.y *= w; c.z *= w; c.w *= w; out[base      ] = c;
            c = pos[base +  32]; c.x *= w; c.y *= w; c.z *= w; c.w *= w; out[base +  32] = c;
            c = pos[base +  64]; c.x *= w; c.y *= w; c.z *= w; c.w *= w; out[base +  64] = c;
            c = pos[base +  96]; c.x *= w; c.y *= w; c.z *= w; c.w *= w; out[base +  96] = c;
        }

        if (!more) return;
        row  = next;
        base = nbase;
    }
}

extern "C" void kernel_launch(void* const* d_in, const int* in_sizes, int n_in,
                              void* d_out, int out_size) {
    const float4* pre = (const float4*)d_in[0];
    const float4* pos = (const float4*)d_in[1];
    float4* out = (float4*)d_out;
    token_mixer_kernel<<<GRID_BLOCKS, WARPS_PER_BLOCK * 32>>>(pre, pos, out);
}

// round 6
// speedup vs baseline: 1.1776x; 1.1776x over previous
#include <cuda_runtime.h>

// TokenMixer: out = x_pos * (1 - sigmoid( <x_pre,x_pos> / (||x_pre||*||x_pos||) ))
// Shapes: [N=4096, B=16, C=512] f32. One warp per row (C=512 = 128 float4).
// R6 (final consolidation): R1 structure — keep x_pos live in registers so
// it is read exactly once; 8 front-batched float4 loads/lane; 3-scalar warp
// tree reduce. Tail trimmed with MUFU.RSQ: 1/max(sqrt(s),eps) == min(rsqrt(s),1e12).
// Measured plateau: ~6.6 TB/s (83% of HBM spec) — the effective ceiling for
// this 2:1 read:write stream; occupancy/MLP/prefetch variants (R2-R5) all
// confirmed no further headroom.

#define ROWS_TOTAL (4096 * 16)
#define F4_PER_ROW 128   // 512 floats / 4
#define WARPS_PER_BLOCK 8

__global__ __launch_bounds__(WARPS_PER_BLOCK * 32)
void token_mixer_kernel(const float4* __restrict__ pre,
                        const float4* __restrict__ pos,
                        float4* __restrict__ out) {
    const int warp_id = threadIdx.x >> 5;
    const int lane    = threadIdx.x & 31;
    const int row     = blockIdx.x * WARPS_PER_BLOCK + warp_id;  // exact: 8192*8 == ROWS_TOTAL

    const size_t base = (size_t)row * F4_PER_ROW + lane;
    const float4* __restrict__ p = pre + base;
    const float4* __restrict__ q = pos + base;

    // Front-batch all 8 loads (coalesced lane + 32*i).
    float4 a0 = p[ 0]; float4 b0 = q[ 0];
    float4 a1 = p[32]; float4 b1 = q[32];
    float4 a2 = p[64]; float4 b2 = q[64];
    float4 a3 = p[96]; float4 b3 = q[96];

    float dot, sa, sb;
    dot  = a0.x*b0.x + a0.y*b0.y + a0.z*b0.z + a0.w*b0.w;
    sa   = a0.x*a0.x + a0.y*a0.y + a0.z*a0.z + a0.w*a0.w;
    sb   = b0.x*b0.x + b0.y*b0.y + b0.z*b0.z + b0.w*b0.w;

    dot += a1.x*b1.x + a1.y*b1.y + a1.z*b1.z + a1.w*b1.w;
    sa  += a1.x*a1.x + a1.y*a1.y + a1.z*a1.z + a1.w*a1.w;
    sb  += b1.x*b1.x + b1.y*b1.y + b1.z*b1.z + b1.w*b1.w;

    dot += a2.x*b2.x + a2.y*b2.y + a2.z*b2.z + a2.w*b2.w;
    sa  += a2.x*a2.x + a2.y*a2.y + a2.z*a2.z + a2.w*a2.w;
    sb  += b2.x*b2.x + b2.y*b2.y + b2.z*b2.z + b2.w*b2.w;

    dot += a3.x*b3.x + a3.y*b3.y + a3.z*b3.z + a3.w*b3.w;
    sa  += a3.x*a3.x + a3.y*a3.y + a3.z*a3.z + a3.w*a3.w;
    sb  += b3.x*b3.x + b3.y*b3.y + b3.z*b3.z + b3.w*b3.w;

    // Warp tree-reduce the three scalars (interleaved chains).
    #pragma unroll
    for (int off = 16; off > 0; off >>= 1) {
        dot += __shfl_xor_sync(0xffffffffu, dot, off);
        sa  += __shfl_xor_sync(0xffffffffu, sa,  off);
        sb  += __shfl_xor_sync(0xffffffffu, sb,  off);
    }

    // 1/max(sqrt(s), 1e-12) == min(rsqrt(s), 1e12): two MUFU.RSQ, no div.
    const float ra = fminf(rsqrtf(sa), 1e12f);
    const float rb = fminf(rsqrtf(sb), 1e12f);
    const float d  = dot * ra * rb;
    // 1 - sigmoid(d) = 1 / (1 + exp(d))
    const float w  = 1.0f / (1.0f + __expf(d));

    float4* __restrict__ o = out + base;
    b0.x *= w; b0.y *= w; b0.z *= w; b0.w *= w;
    b1.x *= w; b1.y *= w; b1.z *= w; b1.w *= w;
    b2.x *= w; b2.y *= w; b2.z *= w; b2.w *= w;
    b3.x *= w; b3.y *= w; b3.z *= w; b3.w *= w;
    o[ 0] = b0;
    o[32] = b1;
    o[64] = b2;
    o[96] = b3;
}

extern "C" void kernel_launch(void* const* d_in, const int* in_sizes, int n_in,
                              void* d_out, int out_size) {
    const float4* pre = (const float4*)d_in[0];
    const float4* pos = (const float4*)d_in[1];
    float4* out = (float4*)d_out;
    const int blocks = ROWS_TOTAL / WARPS_PER_BLOCK;  // 8192
    token_mixer_kernel<<<blocks, WARPS_PER_BLOCK * 32>>>(pre, pos, out);
}

// round 7
// speedup vs baseline: 1.2013x; 1.0201x over previous
#include <cuda_runtime.h>

// TokenMixer: out = x_pos * (1 - sigmoid( <x_pre,x_pos> / (||x_pre||*||x_pos||) ))
// Shapes: [N=4096, B=16, C=512] f32. One warp per row.
// R7: 256-bit global accesses (Blackwell ld/st.global.v8.f32 -> LDG.E.256).
// Halves memory-op count (12 -> 6 per lane) to cut L1tex wavefront/LSU
// pressure; everything else identical to R6 (best: 52.7us, 83.9% DRAM).
// Each lane handles 2 v8-chunks per array: floats [lane*8, lane*8+8) and
// [256 + lane*8, ...) of its 512-float row -> warp covers 1KB per load op.

#define ROWS_TOTAL (4096 * 16)
#define FLOATS_PER_ROW 512
#define WARPS_PER_BLOCK 8

__device__ __forceinline__ void ldg256(const float* __restrict__ p, float r[8]) {
    asm("ld.global.v8.f32 {%0,%1,%2,%3,%4,%5,%6,%7}, [%8];"
        : "=f"(r[0]), "=f"(r[1]), "=f"(r[2]), "=f"(r[3]),
          "=f"(r[4]), "=f"(r[5]), "=f"(r[6]), "=f"(r[7])
        : "l"(p));
}

__device__ __forceinline__ void stg256(float* __restrict__ p, const float r[8]) {
    asm volatile("st.global.v8.f32 [%0], {%1,%2,%3,%4,%5,%6,%7,%8};"
        :: "l"(p),
           "f"(r[0]), "f"(r[1]), "f"(r[2]), "f"(r[3]),
           "f"(r[4]), "f"(r[5]), "f"(r[6]), "f"(r[7])
        : "memory");
}

__global__ __launch_bounds__(WARPS_PER_BLOCK * 32)
void token_mixer_kernel(const float* __restrict__ pre,
                        const float* __restrict__ pos,
                        float* __restrict__ out) {
    const int warp_id = threadIdx.x >> 5;
    const int lane    = threadIdx.x & 31;
    const int row     = blockIdx.x * WARPS_PER_BLOCK + warp_id;  // exact cover

    const size_t base = (size_t)row * FLOATS_PER_ROW + lane * 8;
    const float* __restrict__ p = pre + base;
    const float* __restrict__ q = pos + base;

    // Front-batch: 4 x 256-bit loads (2 per input).
    float a0[8], a1[8], b0[8], b1[8];
    ldg256(p,       a0);
    ldg256(q,       b0);
    ldg256(p + 256, a1);
    ldg256(q + 256, b1);

    float dot = 0.f, sa = 0.f, sb = 0.f;
    #pragma unroll
    for (int i = 0; i < 8; i++) {
        dot += a0[i] * b0[i];
        sa  += a0[i] * a0[i];
        sb  += b0[i] * b0[i];
        dot += a1[i] * b1[i];
        sa  += a1[i] * a1[i];
        sb  += b1[i] * b1[i];
    }

    // Warp tree-reduce the three scalars.
    #pragma unroll
    for (int off = 16; off > 0; off >>= 1) {
        dot += __shfl_xor_sync(0xffffffffu, dot, off);
        sa  += __shfl_xor_sync(0xffffffffu, sa,  off);
        sb  += __shfl_xor_sync(0xffffffffu, sb,  off);
    }

    // 1/max(sqrt(s), 1e-12) == min(rsqrt(s), 1e12): two MUFU.RSQ, no div.
    const float ra = fminf(rsqrtf(sa), 1e12f);
    const float rb = fminf(rsqrtf(sb), 1e12f);
    const float d  = dot * ra * rb;
    // 1 - sigmoid(d) = 1 / (1 + exp(d))
    const float w  = 1.0f / (1.0f + __expf(d));

    #pragma unroll
    for (int i = 0; i < 8; i++) { b0[i] *= w; b1[i] *= w; }

    float* __restrict__ o = out + base;
    stg256(o,       b0);
    stg256(o + 256, b1);
}

extern "C" void kernel_launch(void* const* d_in, const int* in_sizes, int n_in,
                              void* d_out, int out_size) {
    const float* pre = (const float*)d_in[0];
    const float* pos = (const float*)d_in[1];
    float* out = (float*)d_out;
    const int blocks = ROWS_TOTAL / WARPS_PER_BLOCK;  // 8192
    token_mixer_kernel<<<blocks, WARPS_PER_BLOCK * 32>>>(pre, pos, out);
}